// round 5
// baseline (speedup 1.0000x reference)
#include <cuda_runtime.h>
#include <cuda_fp16.h>
#include <cuda_bf16.h>

#define N_NODES 50000
#define N_EDGES 800000
#define DIMS 128

// Scratch: per-node projections in FP16 so BOTH tables (2 x 100 KB = 200 KB)
// fit in a single SM's L1D (~228 KB) -> random gathers become L1 hits
// instead of ~50% L2 round-trips (fp32 tables were 400 KB > L1).
__device__ __half g_psrc16[N_NODES];
__device__ __half g_pdst16[N_NODES];

// Kernel 1: one warp handles TWO nodes. Each lane loads float4 of each node
// row + both weight halves, computes 4 partial dots, shfl-tree reduces.
__global__ void proj_kernel(const float* __restrict__ h,
                            const float* __restrict__ W,
                            const float* __restrict__ b) {
    int gwarp = (blockIdx.x * blockDim.x + threadIdx.x) >> 5;
    int lane  = threadIdx.x & 31;
    int n0 = gwarp * 2;
    if (n0 >= N_NODES) return;
    int n1 = n0 + 1;
    bool has1 = (n1 < N_NODES);

    const float4* ws = reinterpret_cast<const float4*>(W);          // W[0:128]
    const float4* wd = reinterpret_cast<const float4*>(W + DIMS);   // W[128:256]

    float4 hv0 = reinterpret_cast<const float4*>(h + (size_t)n0 * DIMS)[lane];
    float4 hv1 = has1 ? reinterpret_cast<const float4*>(h + (size_t)n1 * DIMS)[lane]
                      : make_float4(0.f, 0.f, 0.f, 0.f);
    float4 wsv = ws[lane];
    float4 wdv = wd[lane];

    float s0 = hv0.x * wsv.x + hv0.y * wsv.y + hv0.z * wsv.z + hv0.w * wsv.w;
    float d0 = hv0.x * wdv.x + hv0.y * wdv.y + hv0.z * wdv.z + hv0.w * wdv.w;
    float s1 = hv1.x * wsv.x + hv1.y * wsv.y + hv1.z * wsv.z + hv1.w * wsv.w;
    float d1 = hv1.x * wdv.x + hv1.y * wdv.y + hv1.z * wdv.z + hv1.w * wdv.w;

    #pragma unroll
    for (int o = 16; o > 0; o >>= 1) {
        s0 += __shfl_xor_sync(0xffffffffu, s0, o);
        d0 += __shfl_xor_sync(0xffffffffu, d0, o);
        s1 += __shfl_xor_sync(0xffffffffu, s1, o);
        d1 += __shfl_xor_sync(0xffffffffu, d1, o);
    }

    if (lane == 0) {
        float bb = b[0];
        g_psrc16[n0] = __float2half_rn(s0);
        g_pdst16[n0] = __float2half_rn(d0 + bb);
        if (has1) {
            g_psrc16[n1] = __float2half_rn(s1);
            g_pdst16[n1] = __float2half_rn(d1 + bb);
        }
    }
}

// Kernel 2: 2 edges per thread. Tables gathered with default (L1-caching)
// loads; streaming index reads use __ldcs and output uses __stcs so they
// do NOT evict table lines from L1.
__global__ void gather_kernel(const int* __restrict__ src,
                              const int* __restrict__ dst,
                              float* __restrict__ out) {
    int i = blockIdx.x * blockDim.x + threadIdx.x;   // pair index
    if (i >= N_EDGES / 2) return;
    int2 s2 = __ldcs(reinterpret_cast<const int2*>(src) + i);
    int2 d2 = __ldcs(reinterpret_cast<const int2*>(dst) + i);
    __half a0 = g_psrc16[s2.x];
    __half b0 = g_pdst16[d2.x];
    __half a1 = g_psrc16[s2.y];
    __half b1 = g_pdst16[d2.y];
    float2 o;
    o.x = __half2float(a0) + __half2float(b0);
    o.y = __half2float(a1) + __half2float(b1);
    __stcs(reinterpret_cast<float2*>(out) + i, o);
}

extern "C" void kernel_launch(void* const* d_in, const int* in_sizes, int n_in,
                              void* d_out, int out_size) {
    const float* h   = (const float*)d_in[0];
    const int*   src = (const int*)d_in[1];
    const int*   dst = (const int*)d_in[2];
    const float* W   = (const float*)d_in[3];
    const float* b   = (const float*)d_in[4];
    float* out = (float*)d_out;

    // Projection: 25000 warps (2 nodes each), 8 warps per block.
    {
        int warps = (N_NODES + 1) / 2;
        int warps_per_block = 8;
        int blocks = (warps + warps_per_block - 1) / warps_per_block;
        proj_kernel<<<blocks, warps_per_block * 32>>>(h, W, b);
    }

    // Gather: 400000 threads (2 edges each; 800000 % 2 == 0).
    {
        int threads = 256;
        int pairs = N_EDGES / 2;
        int blocks = (pairs + threads - 1) / threads;
        gather_kernel<<<blocks, threads>>>(src, dst, out);
    }
}

// round 7
// speedup vs baseline: 1.0915x; 1.0915x over previous
#include <cuda_runtime.h>
#include <cuda_fp16.h>
#include <cuda_bf16.h>

#define N_NODES 50000
#define N_EDGES 800000
#define DIMS 128

#define GATHER_BLOCKS 148
#define GATHER_THREADS 1024
#define TABLE_BYTES (N_NODES * 4)   // __half2 per node = 200000 B smem

// Packed per-node projections: .x (lo) = h[n]·W_src, .y (hi) = h[n]·W_dst + b.
// 200 KB total -> fits in one block's shared memory.
__device__ __half2 g_ptab[N_NODES];

// Kernel 1: one warp handles FOUR nodes (MLP_p1=4 on the streaming 512-B row
// loads). Interleaved shfl tree reduces all 8 dots.
__global__ void proj_kernel(const float* __restrict__ h,
                            const float* __restrict__ W,
                            const float* __restrict__ b) {
    int gwarp = (blockIdx.x * blockDim.x + threadIdx.x) >> 5;
    int lane  = threadIdx.x & 31;
    int n0 = gwarp * 4;
    if (n0 >= N_NODES) return;

    const float4* ws = reinterpret_cast<const float4*>(W);          // W[0:128]
    const float4* wd = reinterpret_cast<const float4*>(W + DIMS);   // W[128:256]
    float4 wsv = ws[lane];
    float4 wdv = wd[lane];

    float s[4], d[4];
    float4 hv[4];
    #pragma unroll
    for (int k = 0; k < 4; k++) {
        int n = n0 + k;
        hv[k] = (n < N_NODES)
              ? reinterpret_cast<const float4*>(h + (size_t)n * DIMS)[lane]
              : make_float4(0.f, 0.f, 0.f, 0.f);
    }
    #pragma unroll
    for (int k = 0; k < 4; k++) {
        s[k] = hv[k].x * wsv.x + hv[k].y * wsv.y + hv[k].z * wsv.z + hv[k].w * wsv.w;
        d[k] = hv[k].x * wdv.x + hv[k].y * wdv.y + hv[k].z * wdv.z + hv[k].w * wdv.w;
    }

    #pragma unroll
    for (int o = 16; o > 0; o >>= 1) {
        #pragma unroll
        for (int k = 0; k < 4; k++) {
            s[k] += __shfl_xor_sync(0xffffffffu, s[k], o);
            d[k] += __shfl_xor_sync(0xffffffffu, d[k], o);
        }
    }

    if (lane == 0) {
        float bb = b[0];
        #pragma unroll
        for (int k = 0; k < 4; k++) {
            int n = n0 + k;
            if (n < N_NODES)
                g_ptab[n] = __floats2half2_rn(s[k], d[k] + bb);
        }
    }
}

// Kernel 2: one block per SM. Phase 1 copies the whole packed table into
// shared memory (broadcast L2 reads). Phase 2 gathers from smem — random
// LDS pays only bank conflicts, bypassing the L1tex wavefront queue that
// bounds global-memory gathers.
__global__ void __launch_bounds__(GATHER_THREADS, 1)
gather_kernel(const int* __restrict__ src,
              const int* __restrict__ dst,
              float* __restrict__ out) {
    extern __shared__ __half2 s_tab[];   // [N_NODES]

    int tid = threadIdx.x;

    // Phase 1: 12500 uint4 (50000 half2) global->smem copy, coalesced.
    {
        const uint4* gt = reinterpret_cast<const uint4*>(g_ptab);
        uint4* st = reinterpret_cast<uint4*>(s_tab);
        #pragma unroll 4
        for (int i = tid; i < N_NODES / 4; i += GATHER_THREADS)
            st[i] = gt[i];
    }
    __syncthreads();

    // Phase 2: contiguous pair-chunk per block, stride-by-block threads.
    int pairs = N_EDGES / 2;                                  // 400000
    int per_block = (pairs + gridDim.x - 1) / gridDim.x;
    int start = blockIdx.x * per_block;
    int end = start + per_block;
    if (end > pairs) end = pairs;

    for (int i = start + tid; i < end; i += GATHER_THREADS) {
        int2 s2 = __ldcs(reinterpret_cast<const int2*>(src) + i);
        int2 d2 = __ldcs(reinterpret_cast<const int2*>(dst) + i);
        float2 o;
        o.x = __low2float(s_tab[s2.x]) + __high2float(s_tab[d2.x]);
        o.y = __low2float(s_tab[s2.y]) + __high2float(s_tab[d2.y]);
        __stcs(reinterpret_cast<float2*>(out) + i, o);
    }
}

extern "C" void kernel_launch(void* const* d_in, const int* in_sizes, int n_in,
                              void* d_out, int out_size) {
    const float* h   = (const float*)d_in[0];
    const int*   src = (const int*)d_in[1];
    const int*   dst = (const int*)d_in[2];
    const float* W   = (const float*)d_in[3];
    const float* b   = (const float*)d_in[4];
    float* out = (float*)d_out;

    // Allow 200 KB dynamic smem for the gather kernel. Called unconditionally
    // every invocation (idempotent host-side attribute set, not an allocation,
    // no static guards -> identical work on every call per harness rules).
    cudaFuncSetAttribute(gather_kernel,
                         cudaFuncAttributeMaxDynamicSharedMemorySize,
                         TABLE_BYTES);

    // Projection: 12500 warps (4 nodes each), 8 warps per block.
    {
        int warps = (N_NODES + 3) / 4;
        int warps_per_block = 8;
        int blocks = (warps + warps_per_block - 1) / warps_per_block;
        proj_kernel<<<blocks, warps_per_block * 32>>>(h, W, b);
    }

    // Gather: one resident block per SM with the full table in smem.
    gather_kernel<<<GATHER_BLOCKS, GATHER_THREADS, TABLE_BYTES>>>(src, dst, out);
}

// round 8
// speedup vs baseline: 1.1451x; 1.0491x over previous
#include <cuda_runtime.h>
#include <cuda_fp16.h>
#include <cuda_bf16.h>
#include <cstdint>

#define N_NODES 50000
#define N_EDGES 800000
#define DIMS 128

#define GATHER_BLOCKS 80
#define GATHER_THREADS 1024
#define PAIRS_PER_BLOCK (N_EDGES / 2 / GATHER_BLOCKS)   // 5000
#define PAIRS_PER_THREAD 5                              // 5*1024 >= 5000
#define TABLE_BYTES (N_NODES * 4)                       // half2/node = 200000 B

// Packed per-node projections: .x (lo) = h[n]·W_src, .y (hi) = h[n]·W_dst + b.
__device__ __half2 g_ptab[N_NODES];

__device__ __forceinline__ uint32_t smem_u32(const void* p) {
    uint32_t a;
    asm("{ .reg .u64 t; cvta.to.shared.u64 t, %1; cvt.u32.u64 %0, t; }"
        : "=r"(a) : "l"(p));
    return a;
}

// Kernel 1: one warp handles FOUR nodes (MLP_p1=4 on the streaming 512-B row
// loads). Interleaved shfl tree reduces all 8 dots.
__global__ void proj_kernel(const float* __restrict__ h,
                            const float* __restrict__ W,
                            const float* __restrict__ b) {
    int gwarp = (blockIdx.x * blockDim.x + threadIdx.x) >> 5;
    int lane  = threadIdx.x & 31;
    int n0 = gwarp * 4;
    if (n0 >= N_NODES) return;

    const float4* ws = reinterpret_cast<const float4*>(W);          // W[0:128]
    const float4* wd = reinterpret_cast<const float4*>(W + DIMS);   // W[128:256]
    float4 wsv = ws[lane];
    float4 wdv = wd[lane];

    float s[4], d[4];
    float4 hv[4];
    #pragma unroll
    for (int k = 0; k < 4; k++) {
        int n = n0 + k;
        hv[k] = (n < N_NODES)
              ? reinterpret_cast<const float4*>(h + (size_t)n * DIMS)[lane]
              : make_float4(0.f, 0.f, 0.f, 0.f);
    }
    #pragma unroll
    for (int k = 0; k < 4; k++) {
        s[k] = hv[k].x * wsv.x + hv[k].y * wsv.y + hv[k].z * wsv.z + hv[k].w * wsv.w;
        d[k] = hv[k].x * wdv.x + hv[k].y * wdv.y + hv[k].z * wdv.z + hv[k].w * wdv.w;
    }

    #pragma unroll
    for (int o = 16; o > 0; o >>= 1) {
        #pragma unroll
        for (int k = 0; k < 4; k++) {
            s[k] += __shfl_xor_sync(0xffffffffu, s[k], o);
            d[k] += __shfl_xor_sync(0xffffffffu, d[k], o);
        }
    }

    if (lane == 0) {
        float bb = b[0];
        #pragma unroll
        for (int k = 0; k < 4; k++) {
            int n = n0 + k;
            if (n < N_NODES)
                g_ptab[n] = __floats2half2_rn(s[k], d[k] + bb);
        }
    }
}

// Kernel 2: per block —
//   (a) elected thread starts an async bulk DMA of the 200 KB table to smem,
//   (b) ALL threads prefetch their edge indices into registers (DRAM latency
//       hidden under the DMA),
//   (c) wait on the mbarrier, then pure smem gather + store.
__global__ void __launch_bounds__(GATHER_THREADS, 1)
gather_kernel(const int* __restrict__ src,
              const int* __restrict__ dst,
              float* __restrict__ out) {
    extern __shared__ __half2 s_tab[];        // [N_NODES], 200000 B
    __shared__ __align__(8) uint64_t s_mbar;

    int tid = threadIdx.x;
    uint32_t mbar = smem_u32(&s_mbar);
    uint32_t tab  = smem_u32(s_tab);

    if (tid == 0) {
        asm volatile("mbarrier.init.shared.b64 [%0], %1;"
                     :: "r"(mbar), "r"(1) : "memory");
    }
    __syncthreads();

    if (tid == 0) {
        asm volatile("mbarrier.arrive.expect_tx.shared.b64 _, [%0], %1;"
                     :: "r"(mbar), "r"((uint32_t)TABLE_BYTES) : "memory");
        asm volatile(
            "cp.async.bulk.shared::cta.global.mbarrier::complete_tx::bytes "
            "[%0], [%1], %2, [%3];"
            :: "r"(tab), "l"((const void*)g_ptab),
               "r"((uint32_t)TABLE_BYTES), "r"(mbar) : "memory");
    }

    // Prefetch indices into registers while the DMA runs.
    int start = blockIdx.x * PAIRS_PER_BLOCK;
    int2 sp[PAIRS_PER_THREAD], dp[PAIRS_PER_THREAD];
    #pragma unroll
    for (int k = 0; k < PAIRS_PER_THREAD; k++) {
        int i = start + tid + k * GATHER_THREADS;
        bool v = (tid + k * GATHER_THREADS) < PAIRS_PER_BLOCK;
        sp[k] = v ? __ldcs(reinterpret_cast<const int2*>(src) + i) : make_int2(0, 0);
        dp[k] = v ? __ldcs(reinterpret_cast<const int2*>(dst) + i) : make_int2(0, 0);
    }

    // Wait for the table DMA.
    {
        uint32_t done;
        asm volatile(
            "{\n\t.reg .pred p;\n\t"
            "mbarrier.try_wait.parity.shared.b64 p, [%1], %2;\n\t"
            "selp.b32 %0, 1, 0, p;\n\t}"
            : "=r"(done) : "r"(mbar), "r"(0u) : "memory");
        while (!done) {
            asm volatile(
                "{\n\t.reg .pred p;\n\t"
                "mbarrier.try_wait.parity.shared.b64 p, [%1], %2, 0x989680;\n\t"
                "selp.b32 %0, 1, 0, p;\n\t}"
                : "=r"(done) : "r"(mbar), "r"(0u) : "memory");
        }
    }

    // Pure smem gather + store.
    #pragma unroll
    for (int k = 0; k < PAIRS_PER_THREAD; k++) {
        if ((tid + k * GATHER_THREADS) < PAIRS_PER_BLOCK) {
            int i = start + tid + k * GATHER_THREADS;
            float2 o;
            o.x = __low2float(s_tab[sp[k].x]) + __high2float(s_tab[dp[k].x]);
            o.y = __low2float(s_tab[sp[k].y]) + __high2float(s_tab[dp[k].y]);
            __stcs(reinterpret_cast<float2*>(out) + i, o);
        }
    }
}

extern "C" void kernel_launch(void* const* d_in, const int* in_sizes, int n_in,
                              void* d_out, int out_size) {
    const float* h   = (const float*)d_in[0];
    const int*   src = (const int*)d_in[1];
    const int*   dst = (const int*)d_in[2];
    const float* W   = (const float*)d_in[3];
    const float* b   = (const float*)d_in[4];
    float* out = (float*)d_out;

    // Allow 200 KB dynamic smem (idempotent host-side attribute set).
    cudaFuncSetAttribute(gather_kernel,
                         cudaFuncAttributeMaxDynamicSharedMemorySize,
                         TABLE_BYTES);

    // Projection: 12500 warps (4 nodes each), 8 warps per block.
    {
        int warps = (N_NODES + 3) / 4;
        int warps_per_block = 8;
        int blocks = (warps + warps_per_block - 1) / warps_per_block;
        proj_kernel<<<blocks, warps_per_block * 32>>>(h, W, b);
    }

    // Gather: 80 blocks x 1024 threads, async table DMA + register-prefetched
    // indices, then smem gather.
    gather_kernel<<<GATHER_BLOCKS, GATHER_THREADS, TABLE_BYTES>>>(src, dst, out);
}